// round 5
// baseline (speedup 1.0000x reference)
#include <cuda_runtime.h>
#include <cuda_fp16.h>

#define H 64
#define IN_DIM 16
#define NMAX 50048
#define EMAX 800000

// scratch (allocation-free rule: __device__ globals)
__device__ float g_dinv[NMAX];
__device__ float g_h[NMAX * H];
__device__ uint2 g_th[NMAX * 16];   // t in half2 pairs: node row = 16 uint2 = 64 halves
__device__ int   g_cnt[NMAX];       // in-degree counts (excl self-loop)
__device__ int   g_rowptr[NMAX + 1];
__device__ int   g_wr[NMAX];        // write cursors for CSR fill
__device__ int   g_src[EMAX];       // CSR: source node per slot
__device__ float g_en[EMAX];        // CSR: edge norm per slot
__device__ int   g_bsum[64];        // scan block sums

// ---------------- CSR build ----------------

__global__ void zero_cnt(int N) {
    int i = blockIdx.x * blockDim.x + threadIdx.x;
    if (i < N) g_cnt[i] = 0;
}

__global__ void count_kernel(const int* __restrict__ col, int E) {
    int e = blockIdx.x * blockDim.x + threadIdx.x;
    if (e < E) atomicAdd(&g_cnt[col[e]], 1);
}

// block-level exclusive scan (1024 elems/block)
__global__ void scanA(int N) {
    __shared__ int s[1024];
    int tid = threadIdx.x;
    int i = blockIdx.x * 1024 + tid;
    int v = (i < N) ? g_cnt[i] : 0;
    s[tid] = v;
    __syncthreads();
    for (int o = 1; o < 1024; o <<= 1) {
        int t = (tid >= o) ? s[tid - o] : 0;
        __syncthreads();
        s[tid] += t;
        __syncthreads();
    }
    if (i < N) g_rowptr[i] = s[tid] - v;  // exclusive within block
    if (tid == 1023) g_bsum[blockIdx.x] = s[1023];
}

// parallel scan over <=64 block sums
__global__ void scanB(int nblk) {
    __shared__ int s[64];
    int t = threadIdx.x;
    int v = (t < nblk) ? g_bsum[t] : 0;
    s[t] = v;
    __syncthreads();
    for (int o = 1; o < 64; o <<= 1) {
        int u = (t >= o) ? s[t - o] : 0;
        __syncthreads();
        s[t] += u;
        __syncthreads();
    }
    if (t < nblk) g_bsum[t] = s[t] - v;  // exclusive
}

__global__ void scanC(int N, int E) {
    int i = blockIdx.x * blockDim.x + threadIdx.x;
    if (i < N) {
        int rp = g_rowptr[i] + g_bsum[i >> 10];
        g_rowptr[i] = rp;
        g_wr[i] = rp;
        g_dinv[i] = rsqrtf((float)g_cnt[i] + 1.0f);  // +1 self-loop
    }
    if (i == 0) g_rowptr[N] = E;
}

__global__ void build_kernel(const int* __restrict__ ei, int E) {
    int e = blockIdx.x * blockDim.x + threadIdx.x;
    if (e >= E) return;
    int r = ei[e], c = ei[E + e];
    int slot = atomicAdd(&g_wr[c], 1);
    g_src[slot] = r;
    g_en[slot] = g_dinv[r] * g_dinv[c];
}

// ---------------- input GEMM: h = relu(x @ W_in + b_in) ----------------

__global__ void in_gemm(const float* __restrict__ x, const float* __restrict__ Win,
                        const float* __restrict__ bin, int N) {
    __shared__ float sW[IN_DIM * H];
    __shared__ float sx[32][IN_DIM];
    int tid = threadIdx.x;
    for (int i = tid; i < IN_DIM * H; i += 256) sW[i] = Win[i];
    int base = blockIdx.x * 32;
    for (int i = tid; i < 32 * IN_DIM; i += 256) {
        int n = i / IN_DIM, k = i % IN_DIM;
        int node = base + n;
        sx[n][k] = (node < N) ? x[node * IN_DIM + k] : 0.0f;
    }
    __syncthreads();
    int j = tid & 63, sub = tid >> 6;
    float bj = bin[j];
    for (int n = sub; n < 32; n += 4) {
        int node = base + n;
        if (node >= N) break;
        float acc = bj;
#pragma unroll
        for (int k = 0; k < IN_DIM; k++) acc += sx[n][k] * sW[k * H + j];
        g_h[node * H + j] = fmaxf(acc, 0.0f);
    }
}

// ---------------- per-layer transform: t = h @ W  (FFMA2, fp16 output) ----------------
// block: 64 nodes x 64 cols, 256 threads. thread = 1 col x 16 nodes (8 f32x2 pairs).
// h tile transposed in shared so node-pairs are contiguous (LDS.128, warp-broadcast).

__device__ __forceinline__ void fma2(unsigned long long& acc, unsigned long long a,
                                     unsigned long long b) {
    asm("fma.rn.f32x2 %0, %1, %2, %3;" : "=l"(acc) : "l"(a), "l"(b), "l"(acc));
}

__global__ void __launch_bounds__(256) conv_gemm(const float* __restrict__ W, int N) {
    __shared__ __align__(16) float shT[64][64];  // shT[k][n], reused as shOut[n][j]
    int tid = threadIdx.x;
    int base = blockIdx.x * 64;

    // load h tile transposed (zero-pad past N)
    for (int i = tid; i < 1024; i += 256) {
        int n = i & 63, q = i >> 6;  // 16 float4 quads per node
        int node = base + n;
        float4 v = (node < N) ? *(const float4*)&g_h[node * H + q * 4]
                              : make_float4(0.f, 0.f, 0.f, 0.f);
        shT[q * 4 + 0][n] = v.x;
        shT[q * 4 + 1][n] = v.y;
        shT[q * 4 + 2][n] = v.z;
        shT[q * 4 + 3][n] = v.w;
    }

    int c = tid & 63;    // output column
    int gq = tid >> 6;   // node group of 16: nodes gq*16 .. gq*16+15

    float w[H];
#pragma unroll
    for (int k = 0; k < H; k++) w[k] = W[k * H + c];  // coalesced across c

    __syncthreads();

    unsigned long long acc[8];
#pragma unroll
    for (int p = 0; p < 8; p++) acc[p] = 0ull;

#pragma unroll 8
    for (int k = 0; k < H; k++) {
        const ulonglong2* ap = (const ulonglong2*)&shT[k][gq * 16];
        ulonglong2 a0 = ap[0], a1 = ap[1], a2 = ap[2], a3 = ap[3];
        unsigned long long bb;
        asm("mov.b64 %0, {%1,%1};" : "=l"(bb) : "f"(w[k]));
        fma2(acc[0], a0.x, bb); fma2(acc[1], a0.y, bb);
        fma2(acc[2], a1.x, bb); fma2(acc[3], a1.y, bb);
        fma2(acc[4], a2.x, bb); fma2(acc[5], a2.y, bb);
        fma2(acc[6], a3.x, bb); fma2(acc[7], a3.y, bb);
    }

    __syncthreads();  // done reading shT; reuse as shOut[n][j]
    float* shOut = &shT[0][0];
#pragma unroll
    for (int p = 0; p < 8; p++) {
        float lo, hi;
        asm("mov.b64 {%0,%1}, %2;" : "=f"(lo), "=f"(hi) : "l"(acc[p]));
        shOut[(gq * 16 + 2 * p + 0) * 64 + c] = lo;
        shOut[(gq * 16 + 2 * p + 1) * 64 + c] = hi;
    }
    __syncthreads();

    // convert + store fp16 rows (coalesced 8B per thread-task)
    for (int i = tid; i < 1024; i += 256) {
        int n = i >> 4, q = i & 15;
        int node = base + n;
        if (node < N) {
            float4 v = *(const float4*)&shOut[n * 64 + q * 4];
            __half2 h0 = __floats2half2_rn(v.x, v.y);
            __half2 h1 = __floats2half2_rn(v.z, v.w);
            g_th[node * 16 + q] = make_uint2(*(unsigned*)&h0, *(unsigned*)&h1);
        }
    }
}

// ---------------- fused gather + bias + self-loop + LN + ReLU + residual (+ head) ----------------
// one warp per node; lane owns features (2*lane, 2*lane+1); messages read as half2

__global__ void gather_ln(const float* __restrict__ b,
                          const float* __restrict__ gamma, const float* __restrict__ beta,
                          const float* __restrict__ Wout, const float* __restrict__ bout,
                          float* __restrict__ out, int N, int last) {
    int node = (blockIdx.x * blockDim.x + threadIdx.x) >> 5;
    int lane = threadIdx.x & 31;
    if (node >= N) return;

    const __half2* t2 = (const __half2*)g_th;
    float d = g_dinv[node];
    float2 b2 = ((const float2*)b)[lane];
    float2 tn = __half22float2(t2[node * 32 + lane]);
    float accx = b2.x + tn.x * d * d;   // bias + self-loop message
    float accy = b2.y + tn.y * d * d;

    int s = g_rowptr[node], e = g_rowptr[node + 1];
    int j = s;
    for (; j + 4 <= e; j += 4) {
        int r0 = g_src[j], r1 = g_src[j + 1], r2 = g_src[j + 2], r3 = g_src[j + 3];
        float n0 = g_en[j], n1 = g_en[j + 1], n2 = g_en[j + 2], n3 = g_en[j + 3];
        float2 v0 = __half22float2(t2[r0 * 32 + lane]);
        float2 v1 = __half22float2(t2[r1 * 32 + lane]);
        float2 v2 = __half22float2(t2[r2 * 32 + lane]);
        float2 v3 = __half22float2(t2[r3 * 32 + lane]);
        accx += v0.x * n0 + v1.x * n1 + v2.x * n2 + v3.x * n3;
        accy += v0.y * n0 + v1.y * n1 + v2.y * n2 + v3.y * n3;
    }
    for (; j < e; ++j) {
        int r = g_src[j];
        float nm = g_en[j];
        float2 v = __half22float2(t2[r * 32 + lane]);
        accx += v.x * nm;
        accy += v.y * nm;
    }

    // layernorm over 64 features
    float ssum = accx + accy;
#pragma unroll
    for (int o = 16; o; o >>= 1) ssum += __shfl_xor_sync(0xFFFFFFFFu, ssum, o);
    float mu = ssum * (1.0f / 64.0f);
    float dx = accx - mu, dy = accy - mu;
    float var = dx * dx + dy * dy;
#pragma unroll
    for (int o = 16; o; o >>= 1) var += __shfl_xor_sync(0xFFFFFFFFu, var, o);
    float inv = rsqrtf(var * (1.0f / 64.0f) + 1e-5f);

    float2 g2 = ((const float2*)gamma)[lane];
    float2 be2 = ((const float2*)beta)[lane];
    float2* hp = (float2*)&g_h[node * H];
    float2 hres = hp[lane];
    float r0 = fmaxf(dx * inv * g2.x + be2.x, 0.0f) + hres.x;
    float r1 = fmaxf(dy * inv * g2.y + be2.y, 0.0f) + hres.y;
    hp[lane] = make_float2(r0, r1);

    if (last) {
        float2 w2 = ((const float2*)Wout)[lane];
        float o_ = r0 * w2.x + r1 * w2.y;
#pragma unroll
        for (int o = 16; o; o >>= 1) o_ += __shfl_xor_sync(0xFFFFFFFFu, o_, o);
        if (lane == 0) out[node] = o_ + bout[0];
    }
}

// ---------------- launch ----------------

extern "C" void kernel_launch(void* const* d_in, const int* in_sizes, int n_in,
                              void* d_out, int out_size) {
    const float* x      = (const float*)d_in[0];
    const int*   ei     = (const int*)d_in[1];
    const float* W_in   = (const float*)d_in[2];
    const float* b_in   = (const float*)d_in[3];
    const float* W_conv = (const float*)d_in[4];
    const float* b_conv = (const float*)d_in[5];
    const float* gamma  = (const float*)d_in[6];
    const float* beta   = (const float*)d_in[7];
    const float* W_out  = (const float*)d_in[8];
    const float* b_out  = (const float*)d_in[9];
    float* out = (float*)d_out;

    int N = in_sizes[0] / IN_DIM;
    int E = in_sizes[1] / 2;
    int nblk_scan = (N + 1023) / 1024;

    // CSR build + dinv
    zero_cnt<<<(N + 255) / 256, 256>>>(N);
    count_kernel<<<(E + 255) / 256, 256>>>(ei + E, E);
    scanA<<<nblk_scan, 1024>>>(N);
    scanB<<<1, 64>>>(nblk_scan);
    scanC<<<(N + 255) / 256, 256>>>(N, E);
    build_kernel<<<(E + 255) / 256, 256>>>(ei, E);

    in_gemm<<<(N + 31) / 32, 256>>>(x, W_in, b_in, N);

    for (int l = 0; l < 3; l++) {
        conv_gemm<<<(N + 63) / 64, 256>>>(W_conv + l * H * H, N);
        gather_ln<<<(N + 7) / 8, 256>>>(b_conv + l * H, gamma + l * H, beta + l * H,
                                        W_out, b_out, out, N, l == 2);
    }
}

// round 6
// speedup vs baseline: 1.1638x; 1.1638x over previous
#include <cuda_runtime.h>
#include <cuda_fp16.h>

#define H 64
#define IN_DIM 16
#define NMAX 50048
#define EMAX 800000

// scratch (allocation-free rule: __device__ globals)
__device__ float  g_dinv[NMAX];
__device__ float  g_h[NMAX * H];
__device__ __half g_th[NMAX * H];   // t stored fp16 (messages)
__device__ int    g_cnt[NMAX];      // in-degree counts (excl self-loop)
__device__ int    g_rowptr[NMAX + 1];
__device__ int    g_wr[NMAX];       // write cursors for CSR fill
__device__ int    g_src[EMAX];      // CSR: source node per slot
__device__ float  g_en[EMAX];       // CSR: edge norm per slot
__device__ int    g_bsum[64];       // scan block sums

// ---------------- CSR build ----------------

__global__ void zero_cnt(int N) {
    int i = blockIdx.x * blockDim.x + threadIdx.x;
    if (i < N) g_cnt[i] = 0;
}

__global__ void count_kernel(const int* __restrict__ col, int E) {
    int e = blockIdx.x * blockDim.x + threadIdx.x;
    if (e < E) atomicAdd(&g_cnt[col[e]], 1);
}

// block-level exclusive scan (1024 elems/block)
__global__ void scanA(int N) {
    __shared__ int s[1024];
    int tid = threadIdx.x;
    int i = blockIdx.x * 1024 + tid;
    int v = (i < N) ? g_cnt[i] : 0;
    s[tid] = v;
    __syncthreads();
    for (int o = 1; o < 1024; o <<= 1) {
        int t = (tid >= o) ? s[tid - o] : 0;
        __syncthreads();
        s[tid] += t;
        __syncthreads();
    }
    if (i < N) g_rowptr[i] = s[tid] - v;  // exclusive within block
    if (tid == 1023) g_bsum[blockIdx.x] = s[1023];
}

// parallel scan over <=64 block sums
__global__ void scanB(int nblk) {
    __shared__ int s[64];
    int t = threadIdx.x;
    int v = (t < nblk) ? g_bsum[t] : 0;
    s[t] = v;
    __syncthreads();
    for (int o = 1; o < 64; o <<= 1) {
        int u = (t >= o) ? s[t - o] : 0;
        __syncthreads();
        s[t] += u;
        __syncthreads();
    }
    if (t < nblk) g_bsum[t] = s[t] - v;  // exclusive
}

__global__ void scanC(int N, int E) {
    int i = blockIdx.x * blockDim.x + threadIdx.x;
    if (i < N) {
        int rp = g_rowptr[i] + g_bsum[i >> 10];
        g_rowptr[i] = rp;
        g_wr[i] = rp;
        g_dinv[i] = rsqrtf((float)g_cnt[i] + 1.0f);  // +1 self-loop
    }
    if (i == 0) g_rowptr[N] = E;
}

__global__ void build_kernel(const int* __restrict__ ei, int E) {
    int e = blockIdx.x * blockDim.x + threadIdx.x;
    if (e >= E) return;
    int r = ei[e], c = ei[E + e];
    int slot = atomicAdd(&g_wr[c], 1);
    g_src[slot] = r;
    g_en[slot] = g_dinv[r] * g_dinv[c];
}

// ---------------- input GEMM: h = relu(x @ W_in + b_in) ----------------

__global__ void in_gemm(const float* __restrict__ x, const float* __restrict__ Win,
                        const float* __restrict__ bin, int N) {
    __shared__ float sW[IN_DIM * H];
    __shared__ float sx[32][IN_DIM];
    int tid = threadIdx.x;
    for (int i = tid; i < IN_DIM * H; i += 256) sW[i] = Win[i];
    int base = blockIdx.x * 32;
    for (int i = tid; i < 32 * IN_DIM; i += 256) {
        int n = i / IN_DIM, k = i % IN_DIM;
        int node = base + n;
        sx[n][k] = (node < N) ? x[node * IN_DIM + k] : 0.0f;
    }
    __syncthreads();
    int j = tid & 63, sub = tid >> 6;
    float bj = bin[j];
    for (int n = sub; n < 32; n += 4) {
        int node = base + n;
        if (node >= N) break;
        float acc = bj;
#pragma unroll
        for (int k = 0; k < IN_DIM; k++) acc += sx[n][k] * sW[k * H + j];
        g_h[node * H + j] = fmaxf(acc, 0.0f);
    }
}

// ---------------- per-layer transform: t = h @ W  (fp32 math, fp16 store) ----------------
// block = 256 threads, 64 nodes per block. W column in registers, h tile in shared.

__global__ void __launch_bounds__(256) conv_gemm(const float* __restrict__ W, int N) {
    __shared__ float sh[64][H];  // 16 KB
    int tid = threadIdx.x;
    int j = tid & 63, sub = tid >> 6;
    int base = blockIdx.x * 64;
    int nn = N - base;
    if (nn > 64) nn = 64;
    if (nn <= 0) return;

    float w[H];
#pragma unroll
    for (int k = 0; k < H; k++) w[k] = W[k * H + j];  // coalesced across j

    const float4* hsrc = (const float4*)&g_h[base * H];
    float4* sdst = (float4*)sh;
    int nvec = nn * (H / 4);
    for (int i = tid; i < nvec; i += 256) sdst[i] = hsrc[i];
    __syncthreads();

    for (int n = sub; n < nn; n += 4) {
        float acc = 0.0f;
#pragma unroll
        for (int k = 0; k < H; k++) acc += sh[n][k] * w[k];
        g_th[(base + n) * H + j] = __float2half_rn(acc);  // 2B coalesced store
    }
}

// ---------------- fused gather + bias + self-loop + LN + ReLU + residual (+ head) ----------------
// one warp per node; lane owns features (2*lane, 2*lane+1); messages read as half2
// (warp reads 128 B per edge row = one L2 line)

__global__ void gather_ln(const float* __restrict__ b,
                          const float* __restrict__ gamma, const float* __restrict__ beta,
                          const float* __restrict__ Wout, const float* __restrict__ bout,
                          float* __restrict__ out, int N, int last) {
    int node = (blockIdx.x * blockDim.x + threadIdx.x) >> 5;
    int lane = threadIdx.x & 31;
    if (node >= N) return;

    const __half2* t2 = (const __half2*)g_th;
    float d = g_dinv[node];
    float2 b2 = ((const float2*)b)[lane];
    float2 tn = __half22float2(t2[node * 32 + lane]);
    float accx = b2.x + tn.x * d * d;   // bias + self-loop message
    float accy = b2.y + tn.y * d * d;

    int s = g_rowptr[node], e = g_rowptr[node + 1];
    int j = s;
    for (; j + 4 <= e; j += 4) {
        int r0 = g_src[j], r1 = g_src[j + 1], r2 = g_src[j + 2], r3 = g_src[j + 3];
        float n0 = g_en[j], n1 = g_en[j + 1], n2 = g_en[j + 2], n3 = g_en[j + 3];
        float2 v0 = __half22float2(t2[r0 * 32 + lane]);
        float2 v1 = __half22float2(t2[r1 * 32 + lane]);
        float2 v2 = __half22float2(t2[r2 * 32 + lane]);
        float2 v3 = __half22float2(t2[r3 * 32 + lane]);
        accx += v0.x * n0 + v1.x * n1 + v2.x * n2 + v3.x * n3;
        accy += v0.y * n0 + v1.y * n1 + v2.y * n2 + v3.y * n3;
    }
    for (; j < e; ++j) {
        int r = g_src[j];
        float nm = g_en[j];
        float2 v = __half22float2(t2[r * 32 + lane]);
        accx += v.x * nm;
        accy += v.y * nm;
    }

    // layernorm over 64 features
    float ssum = accx + accy;
#pragma unroll
    for (int o = 16; o; o >>= 1) ssum += __shfl_xor_sync(0xFFFFFFFFu, ssum, o);
    float mu = ssum * (1.0f / 64.0f);
    float dx = accx - mu, dy = accy - mu;
    float var = dx * dx + dy * dy;
#pragma unroll
    for (int o = 16; o; o >>= 1) var += __shfl_xor_sync(0xFFFFFFFFu, var, o);
    float inv = rsqrtf(var * (1.0f / 64.0f) + 1e-5f);

    float2 g2 = ((const float2*)gamma)[lane];
    float2 be2 = ((const float2*)beta)[lane];
    float2* hp = (float2*)&g_h[node * H];
    float2 hres = hp[lane];
    float r0 = fmaxf(dx * inv * g2.x + be2.x, 0.0f) + hres.x;
    float r1 = fmaxf(dy * inv * g2.y + be2.y, 0.0f) + hres.y;
    hp[lane] = make_float2(r0, r1);

    if (last) {
        float2 w2 = ((const float2*)Wout)[lane];
        float o_ = r0 * w2.x + r1 * w2.y;
#pragma unroll
        for (int o = 16; o; o >>= 1) o_ += __shfl_xor_sync(0xFFFFFFFFu, o_, o);
        if (lane == 0) out[node] = o_ + bout[0];
    }
}

// ---------------- launch ----------------

extern "C" void kernel_launch(void* const* d_in, const int* in_sizes, int n_in,
                              void* d_out, int out_size) {
    const float* x      = (const float*)d_in[0];
    const int*   ei     = (const int*)d_in[1];
    const float* W_in   = (const float*)d_in[2];
    const float* b_in   = (const float*)d_in[3];
    const float* W_conv = (const float*)d_in[4];
    const float* b_conv = (const float*)d_in[5];
    const float* gamma  = (const float*)d_in[6];
    const float* beta   = (const float*)d_in[7];
    const float* W_out  = (const float*)d_in[8];
    const float* b_out  = (const float*)d_in[9];
    float* out = (float*)d_out;

    int N = in_sizes[0] / IN_DIM;
    int E = in_sizes[1] / 2;
    int nblk_scan = (N + 1023) / 1024;

    // CSR build + dinv
    zero_cnt<<<(N + 255) / 256, 256>>>(N);
    count_kernel<<<(E + 255) / 256, 256>>>(ei + E, E);
    scanA<<<nblk_scan, 1024>>>(N);
    scanB<<<1, 64>>>(nblk_scan);
    scanC<<<(N + 255) / 256, 256>>>(N, E);
    build_kernel<<<(E + 255) / 256, 256>>>(ei, E);

    in_gemm<<<(N + 31) / 32, 256>>>(x, W_in, b_in, N);

    for (int l = 0; l < 3; l++) {
        conv_gemm<<<(N + 63) / 64, 256>>>(W_conv + l * H * H, N);
        gather_ln<<<(N + 7) / 8, 256>>>(b_conv + l * H, gamma + l * H, beta + l * H,
                                        W_out, b_out, out, N, l == 2);
    }
}

// round 7
// speedup vs baseline: 1.2196x; 1.0480x over previous
#include <cuda_runtime.h>
#include <cuda_fp16.h>

#define H 64
#define IN_DIM 16
#define NMAX 50048
#define EMAX 800000

// scratch (allocation-free rule: __device__ globals)
__device__ float  g_dinv[NMAX];
__device__ float  g_h[NMAX * H];
__device__ __half g_th[NMAX * H];   // t stored fp16 (messages)
__device__ int    g_cnt[NMAX];      // in-degree counts (excl self-loop)
__device__ int    g_rowptr[NMAX + 1];
__device__ int    g_wr[NMAX];       // write cursors for CSR fill
__device__ int2   g_se[EMAX];       // CSR: packed {src, norm-as-int} per slot
__device__ int    g_bsum[64];       // scan block sums

// ---------------- CSR build ----------------

__global__ void count_kernel(const int* __restrict__ col, int E) {
    int e = blockIdx.x * blockDim.x + threadIdx.x;
    if (e < E) atomicAdd(&g_cnt[col[e]], 1);
}

// block-level exclusive scan (1024 elems/block)
__global__ void scanA(int N) {
    __shared__ int s[1024];
    int tid = threadIdx.x;
    int i = blockIdx.x * 1024 + tid;
    int v = (i < N) ? g_cnt[i] : 0;
    s[tid] = v;
    __syncthreads();
    for (int o = 1; o < 1024; o <<= 1) {
        int t = (tid >= o) ? s[tid - o] : 0;
        __syncthreads();
        s[tid] += t;
        __syncthreads();
    }
    if (i < N) g_rowptr[i] = s[tid] - v;  // exclusive within block
    if (tid == 1023) g_bsum[blockIdx.x] = s[1023];
}

// finalize rowptr: each 256-block computes its 1024-segment's bsum prefix in-warp
__global__ void scanC(int N, int E) {
    __shared__ int sbase;
    int i = blockIdx.x * 256 + threadIdx.x;
    int seg = (blockIdx.x * 256) >> 10;  // all threads of block share one segment
    if (threadIdx.x < 32) {
        int l = threadIdx.x;
        int v = ((l < seg) ? g_bsum[l] : 0) + ((l + 32 < seg) ? g_bsum[l + 32] : 0);
#pragma unroll
        for (int o = 16; o; o >>= 1) v += __shfl_xor_sync(0xFFFFFFFFu, v, o);
        if (l == 0) sbase = v;
    }
    __syncthreads();
    if (i < N) {
        int rp = g_rowptr[i] + sbase;
        g_rowptr[i] = rp;
        g_wr[i] = rp;
        g_dinv[i] = rsqrtf((float)g_cnt[i] + 1.0f);  // +1 self-loop
    }
    if (i == 0) g_rowptr[N] = E;
}

__global__ void build_kernel(const int* __restrict__ ei, int E) {
    int e = blockIdx.x * blockDim.x + threadIdx.x;
    if (e >= E) return;
    int r = ei[e], c = ei[E + e];
    int slot = atomicAdd(&g_wr[c], 1);
    g_se[slot] = make_int2(r, __float_as_int(g_dinv[r] * g_dinv[c]));
}

// ---------------- input GEMM: h = relu(x @ W_in + b_in) ----------------

__global__ void in_gemm(const float* __restrict__ x, const float* __restrict__ Win,
                        const float* __restrict__ bin, int N) {
    __shared__ float sW[IN_DIM * H];
    __shared__ float sx[32][IN_DIM];
    int tid = threadIdx.x;
    for (int i = tid; i < IN_DIM * H; i += 256) sW[i] = Win[i];
    int base = blockIdx.x * 32;
    for (int i = tid; i < 32 * IN_DIM; i += 256) {
        int n = i / IN_DIM, k = i % IN_DIM;
        int node = base + n;
        sx[n][k] = (node < N) ? x[node * IN_DIM + k] : 0.0f;
    }
    __syncthreads();
    int j = tid & 63, sub = tid >> 6;
    float bj = bin[j];
    for (int n = sub; n < 32; n += 4) {
        int node = base + n;
        if (node >= N) break;
        float acc = bj;
#pragma unroll
        for (int k = 0; k < IN_DIM; k++) acc += sx[n][k] * sW[k * H + j];
        g_h[node * H + j] = fmaxf(acc, 0.0f);
    }
}

// ---------------- per-layer transform: t = h @ W  (fp32 math, fp16 store) ----------------
// block = 256 threads, 64 nodes per block. W column in registers, h tile in shared.
// inner product via explicit LDS.128: 1 shared load per 4 FMAs (broadcast, conflict-free).

__global__ void __launch_bounds__(256) conv_gemm(const float* __restrict__ W, int N) {
    __shared__ __align__(16) float sh[64][H];  // 16 KB, rows 256B-aligned
    int tid = threadIdx.x;
    int j = tid & 63, sub = tid >> 6;
    int base = blockIdx.x * 64;
    int nn = N - base;
    if (nn > 64) nn = 64;
    if (nn <= 0) return;

    float w[H];
#pragma unroll
    for (int k = 0; k < H; k++) w[k] = W[k * H + j];  // coalesced across j

    const float4* hsrc = (const float4*)&g_h[base * H];
    float4* sdst = (float4*)sh;
    int nvec = nn * (H / 4);
    for (int i = tid; i < nvec; i += 256) sdst[i] = hsrc[i];
    __syncthreads();

    for (int n = sub; n < nn; n += 4) {
        const float4* sp = (const float4*)&sh[n][0];
        float acc = 0.0f;
#pragma unroll
        for (int q = 0; q < 16; q++) {
            float4 s = sp[q];
            acc += s.x * w[4 * q] + s.y * w[4 * q + 1] + s.z * w[4 * q + 2] + s.w * w[4 * q + 3];
        }
        g_th[(base + n) * H + j] = __float2half_rn(acc);  // 2B coalesced store
    }
}

// ---------------- fused gather + bias + self-loop + LN + ReLU + residual (+ head) ----------------
// one warp per node; lane owns features (2*lane, 2*lane+1); messages read as half2.
// unroll-8 edge loop: 8 uniform LDG.64 metadata + 8 gather LDG.64 in flight.

__global__ void gather_ln(const float* __restrict__ b,
                          const float* __restrict__ gamma, const float* __restrict__ beta,
                          const float* __restrict__ Wout, const float* __restrict__ bout,
                          float* __restrict__ out, int N, int last) {
    int node = (blockIdx.x * blockDim.x + threadIdx.x) >> 5;
    int lane = threadIdx.x & 31;
    if (node >= N) return;

    const __half2* t2 = (const __half2*)g_th;
    float d = g_dinv[node];
    float2 b2 = ((const float2*)b)[lane];
    float2 tn = __half22float2(t2[node * 32 + lane]);
    float accx = b2.x + tn.x * d * d;   // bias + self-loop message
    float accy = b2.y + tn.y * d * d;

    int s = g_rowptr[node], e = g_rowptr[node + 1];
    int j = s;
    for (; j + 8 <= e; j += 8) {
        int2 m0 = g_se[j],     m1 = g_se[j + 1], m2 = g_se[j + 2], m3 = g_se[j + 3];
        int2 m4 = g_se[j + 4], m5 = g_se[j + 5], m6 = g_se[j + 6], m7 = g_se[j + 7];
        float2 v0 = __half22float2(t2[m0.x * 32 + lane]);
        float2 v1 = __half22float2(t2[m1.x * 32 + lane]);
        float2 v2 = __half22float2(t2[m2.x * 32 + lane]);
        float2 v3 = __half22float2(t2[m3.x * 32 + lane]);
        float2 v4 = __half22float2(t2[m4.x * 32 + lane]);
        float2 v5 = __half22float2(t2[m5.x * 32 + lane]);
        float2 v6 = __half22float2(t2[m6.x * 32 + lane]);
        float2 v7 = __half22float2(t2[m7.x * 32 + lane]);
        accx += v0.x * __int_as_float(m0.y) + v1.x * __int_as_float(m1.y)
              + v2.x * __int_as_float(m2.y) + v3.x * __int_as_float(m3.y)
              + v4.x * __int_as_float(m4.y) + v5.x * __int_as_float(m5.y)
              + v6.x * __int_as_float(m6.y) + v7.x * __int_as_float(m7.y);
        accy += v0.y * __int_as_float(m0.y) + v1.y * __int_as_float(m1.y)
              + v2.y * __int_as_float(m2.y) + v3.y * __int_as_float(m3.y)
              + v4.y * __int_as_float(m4.y) + v5.y * __int_as_float(m5.y)
              + v6.y * __int_as_float(m6.y) + v7.y * __int_as_float(m7.y);
    }
    for (; j < e; ++j) {
        int2 m = g_se[j];
        float nm = __int_as_float(m.y);
        float2 v = __half22float2(t2[m.x * 32 + lane]);
        accx += v.x * nm;
        accy += v.y * nm;
    }

    // layernorm over 64 features
    float ssum = accx + accy;
#pragma unroll
    for (int o = 16; o; o >>= 1) ssum += __shfl_xor_sync(0xFFFFFFFFu, ssum, o);
    float mu = ssum * (1.0f / 64.0f);
    float dx = accx - mu, dy = accy - mu;
    float var = dx * dx + dy * dy;
#pragma unroll
    for (int o = 16; o; o >>= 1) var += __shfl_xor_sync(0xFFFFFFFFu, var, o);
    float inv = rsqrtf(var * (1.0f / 64.0f) + 1e-5f);

    float2 g2 = ((const float2*)gamma)[lane];
    float2 be2 = ((const float2*)beta)[lane];
    float2* hp = (float2*)&g_h[node * H];
    float2 hres = hp[lane];
    float r0 = fmaxf(dx * inv * g2.x + be2.x, 0.0f) + hres.x;
    float r1 = fmaxf(dy * inv * g2.y + be2.y, 0.0f) + hres.y;
    hp[lane] = make_float2(r0, r1);

    if (last) {
        float2 w2 = ((const float2*)Wout)[lane];
        float o_ = r0 * w2.x + r1 * w2.y;
#pragma unroll
        for (int o = 16; o; o >>= 1) o_ += __shfl_xor_sync(0xFFFFFFFFu, o_, o);
        if (lane == 0) out[node] = o_ + bout[0];
    }
}

// ---------------- launch ----------------

extern "C" void kernel_launch(void* const* d_in, const int* in_sizes, int n_in,
                              void* d_out, int out_size) {
    const float* x      = (const float*)d_in[0];
    const int*   ei     = (const int*)d_in[1];
    const float* W_in   = (const float*)d_in[2];
    const float* b_in   = (const float*)d_in[3];
    const float* W_conv = (const float*)d_in[4];
    const float* b_conv = (const float*)d_in[5];
    const float* gamma  = (const float*)d_in[6];
    const float* beta   = (const float*)d_in[7];
    const float* W_out  = (const float*)d_in[8];
    const float* b_out  = (const float*)d_in[9];
    float* out = (float*)d_out;

    int N = in_sizes[0] / IN_DIM;
    int E = in_sizes[1] / 2;
    int nblk_scan = (N + 1023) / 1024;

    // CSR build + dinv
    void* cnt_ptr = nullptr;
    cudaGetSymbolAddress(&cnt_ptr, g_cnt);
    cudaMemsetAsync(cnt_ptr, 0, (size_t)N * sizeof(int));
    count_kernel<<<(E + 255) / 256, 256>>>(ei + E, E);
    scanA<<<nblk_scan, 1024>>>(N);
    scanC<<<(N + 255) / 256, 256>>>(N, E);
    build_kernel<<<(E + 255) / 256, 256>>>(ei, E);

    in_gemm<<<(N + 31) / 32, 256>>>(x, W_in, b_in, N);

    for (int l = 0; l < 3; l++) {
        conv_gemm<<<(N + 63) / 64, 256>>>(W_conv + l * H * H, N);
        gather_ln<<<(N + 7) / 8, 256>>>(b_conv + l * H, gamma + l * H, beta + l * H,
                                        W_out, b_out, out, N, l == 2);
    }
}

// round 8
// speedup vs baseline: 1.2429x; 1.0191x over previous
#include <cuda_runtime.h>
#include <cuda_fp16.h>

#define H 64
#define IN_DIM 16
#define NMAX 50048
#define EMAX 800000

// scratch (allocation-free rule: __device__ globals)
__device__ float    g_dinv[NMAX];
__device__ float    g_h[NMAX * H];
__device__ __half   g_th[NMAX * H];     // t stored fp16 (messages)
__device__ int      g_cnt[NMAX];        // in-degree counts (excl self-loop)
__device__ int      g_rowptr[NMAX + 1];
__device__ int      g_wr[NMAX];         // write cursors for CSR fill
__device__ unsigned g_se[EMAX];         // CSR: packed {norm:f16 <<16 | src:u16}
__device__ int      g_bsum[64];         // scan block sums

// ---------------- CSR build ----------------

__global__ void count_kernel(const int* __restrict__ col, int E) {
    int e = blockIdx.x * blockDim.x + threadIdx.x;
    if (e < E) atomicAdd(&g_cnt[col[e]], 1);
}

// block-level exclusive scan (1024 elems/block)
__global__ void scanA(int N) {
    __shared__ int s[1024];
    int tid = threadIdx.x;
    int i = blockIdx.x * 1024 + tid;
    int v = (i < N) ? g_cnt[i] : 0;
    s[tid] = v;
    __syncthreads();
    for (int o = 1; o < 1024; o <<= 1) {
        int t = (tid >= o) ? s[tid - o] : 0;
        __syncthreads();
        s[tid] += t;
        __syncthreads();
    }
    if (i < N) g_rowptr[i] = s[tid] - v;  // exclusive within block
    if (tid == 1023) g_bsum[blockIdx.x] = s[1023];
}

// finalize rowptr: each 256-block computes its 1024-segment's bsum prefix in-warp
__global__ void scanC(int N, int E) {
    __shared__ int sbase;
    int i = blockIdx.x * 256 + threadIdx.x;
    int seg = (blockIdx.x * 256) >> 10;  // all threads of block share one segment
    if (threadIdx.x < 32) {
        int l = threadIdx.x;
        int v = ((l < seg) ? g_bsum[l] : 0) + ((l + 32 < seg) ? g_bsum[l + 32] : 0);
#pragma unroll
        for (int o = 16; o; o >>= 1) v += __shfl_xor_sync(0xFFFFFFFFu, v, o);
        if (l == 0) sbase = v;
    }
    __syncthreads();
    if (i < N) {
        int rp = g_rowptr[i] + sbase;
        g_rowptr[i] = rp;
        g_wr[i] = rp;
        g_dinv[i] = rsqrtf((float)g_cnt[i] + 1.0f);  // +1 self-loop
    }
    if (i == 0) g_rowptr[N] = E;
}

__global__ void build_kernel(const int* __restrict__ ei, int E) {
    int e = blockIdx.x * blockDim.x + threadIdx.x;
    if (e >= E) return;
    int r = ei[e], c = ei[E + e];
    int slot = atomicAdd(&g_wr[c], 1);
    __half nh = __float2half_rn(g_dinv[r] * g_dinv[c]);
    g_se[slot] = ((unsigned)__half_as_ushort(nh) << 16) | (unsigned)r;  // src < 65536
}

// ---------------- input GEMM: h = relu(x @ W_in + b_in) ----------------

__global__ void in_gemm(const float* __restrict__ x, const float* __restrict__ Win,
                        const float* __restrict__ bin, int N) {
    __shared__ float sW[IN_DIM * H];
    __shared__ float sx[32][IN_DIM];
    int tid = threadIdx.x;
    for (int i = tid; i < IN_DIM * H; i += 256) sW[i] = Win[i];
    int base = blockIdx.x * 32;
    for (int i = tid; i < 32 * IN_DIM; i += 256) {
        int n = i / IN_DIM, k = i % IN_DIM;
        int node = base + n;
        sx[n][k] = (node < N) ? x[node * IN_DIM + k] : 0.0f;
    }
    __syncthreads();
    int j = tid & 63, sub = tid >> 6;
    float bj = bin[j];
    for (int n = sub; n < 32; n += 4) {
        int node = base + n;
        if (node >= N) break;
        float acc = bj;
#pragma unroll
        for (int k = 0; k < IN_DIM; k++) acc += sx[n][k] * sW[k * H + j];
        g_h[node * H + j] = fmaxf(acc, 0.0f);
    }
}

// ---------------- per-layer transform: t = h @ W  (fp32 math, fp16 store) ----------------

__global__ void __launch_bounds__(256) conv_gemm(const float* __restrict__ W, int N) {
    __shared__ __align__(16) float sh[64][H];  // 16 KB
    int tid = threadIdx.x;
    int j = tid & 63, sub = tid >> 6;
    int base = blockIdx.x * 64;
    int nn = N - base;
    if (nn > 64) nn = 64;
    if (nn <= 0) return;

    float w[H];
#pragma unroll
    for (int k = 0; k < H; k++) w[k] = W[k * H + j];  // coalesced across j

    const float4* hsrc = (const float4*)&g_h[base * H];
    float4* sdst = (float4*)sh;
    int nvec = nn * (H / 4);
    for (int i = tid; i < nvec; i += 256) sdst[i] = hsrc[i];
    __syncthreads();

    for (int n = sub; n < nn; n += 4) {
        const float4* sp = (const float4*)&sh[n][0];
        float acc = 0.0f;
#pragma unroll
        for (int q = 0; q < 16; q++) {
            float4 s = sp[q];
            acc += s.x * w[4 * q] + s.y * w[4 * q + 1] + s.z * w[4 * q + 2] + s.w * w[4 * q + 3];
        }
        g_th[(base + n) * H + j] = __float2half_rn(acc);  // 2B coalesced store
    }
}

// ---------------- fused gather + bias + self-loop + LN + ReLU + residual (+ head) ----------------
// one warp per node; lane owns features (2*lane, 2*lane+1); messages read as half2.

__device__ __forceinline__ void unpack_se(unsigned m, int& src, float& nm) {
    src = (int)(m & 0xFFFFu);
    nm = __half2float(__ushort_as_half((unsigned short)(m >> 16)));
}

__global__ void gather_ln(const float* __restrict__ b,
                          const float* __restrict__ gamma, const float* __restrict__ beta,
                          const float* __restrict__ Wout, const float* __restrict__ bout,
                          float* __restrict__ out, int N, int last) {
    int node = (blockIdx.x * blockDim.x + threadIdx.x) >> 5;
    int lane = threadIdx.x & 31;
    if (node >= N) return;

    const __half2* t2 = (const __half2*)g_th;
    float d = g_dinv[node];
    float2 b2 = ((const float2*)b)[lane];
    float2 tn = __half22float2(t2[node * 32 + lane]);
    float accx = b2.x + tn.x * d * d;   // bias + self-loop message
    float accy = b2.y + tn.y * d * d;

    int s = g_rowptr[node], e = g_rowptr[node + 1];
    int j = s;
    for (; j + 8 <= e; j += 8) {
        int r0, r1, r2, r3, r4, r5, r6, r7;
        float n0, n1, n2, n3, n4, n5, n6, n7;
        unpack_se(g_se[j],     r0, n0); unpack_se(g_se[j + 1], r1, n1);
        unpack_se(g_se[j + 2], r2, n2); unpack_se(g_se[j + 3], r3, n3);
        unpack_se(g_se[j + 4], r4, n4); unpack_se(g_se[j + 5], r5, n5);
        unpack_se(g_se[j + 6], r6, n6); unpack_se(g_se[j + 7], r7, n7);
        float2 v0 = __half22float2(t2[r0 * 32 + lane]);
        float2 v1 = __half22float2(t2[r1 * 32 + lane]);
        float2 v2 = __half22float2(t2[r2 * 32 + lane]);
        float2 v3 = __half22float2(t2[r3 * 32 + lane]);
        float2 v4 = __half22float2(t2[r4 * 32 + lane]);
        float2 v5 = __half22float2(t2[r5 * 32 + lane]);
        float2 v6 = __half22float2(t2[r6 * 32 + lane]);
        float2 v7 = __half22float2(t2[r7 * 32 + lane]);
        accx += v0.x * n0 + v1.x * n1 + v2.x * n2 + v3.x * n3
              + v4.x * n4 + v5.x * n5 + v6.x * n6 + v7.x * n7;
        accy += v0.y * n0 + v1.y * n1 + v2.y * n2 + v3.y * n3
              + v4.y * n4 + v5.y * n5 + v6.y * n6 + v7.y * n7;
    }
    for (; j < e; ++j) {
        int r; float nm;
        unpack_se(g_se[j], r, nm);
        float2 v = __half22float2(t2[r * 32 + lane]);
        accx += v.x * nm;
        accy += v.y * nm;
    }

    // layernorm over 64 features
    float ssum = accx + accy;
#pragma unroll
    for (int o = 16; o; o >>= 1) ssum += __shfl_xor_sync(0xFFFFFFFFu, ssum, o);
    float mu = ssum * (1.0f / 64.0f);
    float dx = accx - mu, dy = accy - mu;
    float var = dx * dx + dy * dy;
#pragma unroll
    for (int o = 16; o; o >>= 1) var += __shfl_xor_sync(0xFFFFFFFFu, var, o);
    float inv = rsqrtf(var * (1.0f / 64.0f) + 1e-5f);

    float2 g2 = ((const float2*)gamma)[lane];
    float2 be2 = ((const float2*)beta)[lane];
    float2* hp = (float2*)&g_h[node * H];
    float2 hres = hp[lane];
    float r0 = fmaxf(dx * inv * g2.x + be2.x, 0.0f) + hres.x;
    float r1 = fmaxf(dy * inv * g2.y + be2.y, 0.0f) + hres.y;
    hp[lane] = make_float2(r0, r1);

    if (last) {
        float2 w2 = ((const float2*)Wout)[lane];
        float o_ = r0 * w2.x + r1 * w2.y;
#pragma unroll
        for (int o = 16; o; o >>= 1) o_ += __shfl_xor_sync(0xFFFFFFFFu, o_, o);
        if (lane == 0) out[node] = o_ + bout[0];
    }
}

// ---------------- launch ----------------

extern "C" void kernel_launch(void* const* d_in, const int* in_sizes, int n_in,
                              void* d_out, int out_size) {
    const float* x      = (const float*)d_in[0];
    const int*   ei     = (const int*)d_in[1];
    const float* W_in   = (const float*)d_in[2];
    const float* b_in   = (const float*)d_in[3];
    const float* W_conv = (const float*)d_in[4];
    const float* b_conv = (const float*)d_in[5];
    const float* gamma  = (const float*)d_in[6];
    const float* beta   = (const float*)d_in[7];
    const float* W_out  = (const float*)d_in[8];
    const float* b_out  = (const float*)d_in[9];
    float* out = (float*)d_out;

    int N = in_sizes[0] / IN_DIM;
    int E = in_sizes[1] / 2;
    int nblk_scan = (N + 1023) / 1024;

    // fork a side stream off the capturing (legacy default) stream:
    // CSR chain on stream 0, in_gemm + conv0 on s2, join before gather l0.
    cudaStream_t s2;
    cudaStreamCreate(&s2);
    cudaEvent_t e0, e1;
    cudaEventCreate(&e0);
    cudaEventCreate(&e1);
    cudaEventRecord(e0, 0);
    cudaStreamWaitEvent(s2, e0, 0);

    // branch B (independent of CSR): input GEMM + layer-0 transform
    in_gemm<<<(N + 31) / 32, 256, 0, s2>>>(x, W_in, b_in, N);
    conv_gemm<<<(N + 63) / 64, 256, 0, s2>>>(W_conv, N);
    cudaEventRecord(e1, s2);

    // branch A: CSR build + dinv
    void* cnt_ptr = nullptr;
    cudaGetSymbolAddress(&cnt_ptr, g_cnt);
    cudaMemsetAsync(cnt_ptr, 0, (size_t)N * sizeof(int));
    count_kernel<<<(E + 255) / 256, 256>>>(ei + E, E);
    scanA<<<nblk_scan, 1024>>>(N);
    scanC<<<(N + 255) / 256, 256>>>(N, E);
    build_kernel<<<(E + 255) / 256, 256>>>(ei, E);

    // join
    cudaStreamWaitEvent(0, e1, 0);

    for (int l = 0; l < 3; l++) {
        if (l > 0) conv_gemm<<<(N + 63) / 64, 256>>>(W_conv + l * H * H, N);
        gather_ln<<<(N + 7) / 8, 256>>>(b_conv + l * H, gamma + l * H, beta + l * H,
                                        W_out, b_out, out, N, l == 2);
    }

    cudaEventDestroy(e0);
    cudaEventDestroy(e1);
    cudaStreamDestroy(s2);
}